// round 15
// baseline (speedup 1.0000x reference)
#include <cuda_runtime.h>
#include <cuda_bf16.h>
#include <cuda_fp16.h>
#include <math.h>
#include <stdint.h>

#define B_  2
#define S_  2048
#define D_  1024
#define H_  16
#define DK_ 64
#define M_  (B_*S_)   // 4096

#define LO_SCALE 4096.0f
#define LO_INV   (1.0f/4096.0f)

// ---- scratch (static device globals; no allocation allowed) ----
__device__ float g_S[(size_t)B_*H_*S_*S_];                 // fp32 scores (512MB)
__device__ __half g_Pf[(size_t)B_*H_*S_*S_];               // probs fp16 (256MB)
__device__ __half g_Qh[(size_t)M_*D_], g_Ql[(size_t)M_*D_];   // lo scaled x4096
__device__ __half g_Kh[(size_t)M_*D_], g_Kl[(size_t)M_*D_];
__device__ __half g_Vh[(size_t)M_*D_];
__device__ __half g_HOh[(size_t)M_*D_];
__device__ __half g_xqh[(size_t)M_*D_], g_xql[(size_t)M_*D_];
__device__ __half g_xkh[(size_t)M_*D_], g_xkl[(size_t)M_*D_];
__device__ __half g_xvh[(size_t)M_*D_], g_xvl[(size_t)M_*D_];
__device__ __half g_wqh[(size_t)D_*D_], g_wql[(size_t)D_*D_];
__device__ __half g_wkh[(size_t)D_*D_], g_wkl[(size_t)D_*D_];
__device__ __half g_wvh[(size_t)D_*D_], g_wvl[(size_t)D_*D_];
__device__ __half g_woh[(size_t)D_*D_], g_wol[(size_t)D_*D_];

// ============================================================
// helpers
// ============================================================
__device__ __forceinline__ uint32_t smem_u32(const void* p) {
    return (uint32_t)__cvta_generic_to_shared(p);
}
__device__ __forceinline__ void cpasync16(void* s, const void* g) {
    asm volatile("cp.async.cg.shared.global [%0], [%1], 16;\n"
                 :: "r"(smem_u32(s)), "l"(g));
}
#define CP_COMMIT() asm volatile("cp.async.commit_group;\n" ::)
#define CP_WAIT1()  asm volatile("cp.async.wait_group 1;\n" ::)

__device__ __forceinline__ void ldsm_x4(uint32_t* r, uint32_t a) {
    asm volatile("ldmatrix.sync.aligned.m8n8.x4.shared.b16 {%0,%1,%2,%3}, [%4];"
                 : "=r"(r[0]), "=r"(r[1]), "=r"(r[2]), "=r"(r[3]) : "r"(a));
}
__device__ __forceinline__ void ldsm_x4_t(uint32_t* r, uint32_t a) {
    asm volatile("ldmatrix.sync.aligned.m8n8.x4.trans.shared.b16 {%0,%1,%2,%3}, [%4];"
                 : "=r"(r[0]), "=r"(r[1]), "=r"(r[2]), "=r"(r[3]) : "r"(a));
}
// fp16 inputs, fp32 accumulator
__device__ __forceinline__ void mma_f16_f32(float* c, const uint32_t* a,
                                            uint32_t b0, uint32_t b1) {
    asm volatile(
        "mma.sync.aligned.m16n8k16.row.col.f32.f16.f16.f32 "
        "{%0,%1,%2,%3},{%4,%5,%6,%7},{%8,%9},{%0,%1,%2,%3};"
        : "+f"(c[0]), "+f"(c[1]), "+f"(c[2]), "+f"(c[3])
        : "r"(a[0]), "r"(a[1]), "r"(a[2]), "r"(a[3]), "r"(b0), "r"(b1));
}
// fp16 inputs, fp16 accumulator (2 packed regs)
__device__ __forceinline__ void mma_f16_f16(uint32_t* c, const uint32_t* a,
                                            uint32_t b0, uint32_t b1) {
    asm volatile(
        "mma.sync.aligned.m16n8k16.row.col.f16.f16.f16.f16 "
        "{%0,%1},{%2,%3,%4,%5},{%6,%7},{%0,%1};"
        : "+r"(c[0]), "+r"(c[1])
        : "r"(a[0]), "r"(a[1]), "r"(a[2]), "r"(a[3]), "r"(b0), "r"(b1));
}

// fp32 -> fp16 hi + scaled lo (lo stored x4096, exact)
__device__ __forceinline__ void split1hs(float v, __half& h, __half& l) {
    h = __float2half_rn(v);
    l = __float2half_rn((v - __half2float(h)) * LO_SCALE);
}

// ============================================================
// one-shot grid-stride converter: all tensors -> fp16 hi + scaled lo
// ============================================================
#define NX4 ((M_*D_)/4)
#define NW4 ((D_*D_)/4)
__global__ __launch_bounds__(256) void split_convert_all(
    const float* __restrict__ xq, const float* __restrict__ xk,
    const float* __restrict__ xv, const float* __restrict__ wq,
    const float* __restrict__ wk, const float* __restrict__ wv,
    const float* __restrict__ wo,
    __half* __restrict__ xqh, __half* __restrict__ xql,
    __half* __restrict__ xkh, __half* __restrict__ xkl,
    __half* __restrict__ xvh, __half* __restrict__ xvl,
    __half* __restrict__ wqh, __half* __restrict__ wql,
    __half* __restrict__ wkh, __half* __restrict__ wkl,
    __half* __restrict__ wvh, __half* __restrict__ wvl,
    __half* __restrict__ woh, __half* __restrict__ wol)
{
    const int total = 3 * NX4 + 4 * NW4;
    for (int i = blockIdx.x * blockDim.x + threadIdx.x; i < total;
         i += gridDim.x * blockDim.x) {
        const float* src; __half *fh, *fl; int j = i;
        if (j < NX4)               { src = xq; fh = xqh; fl = xql; }
        else if ((j -= NX4) < NX4) { src = xk; fh = xkh; fl = xkl; }
        else if ((j -= NX4) < NX4) { src = xv; fh = xvh; fl = xvl; }
        else if ((j -= NX4) < NW4) { src = wq; fh = wqh; fl = wql; }
        else if ((j -= NW4) < NW4) { src = wk; fh = wkh; fl = wkl; }
        else if ((j -= NW4) < NW4) { src = wv; fh = wvh; fl = wvl; }
        else      { j -= NW4;        src = wo; fh = woh; fl = wol; }
        float4 v = *(const float4*)(src + (size_t)j * 4);
        __half h0,h1,h2,h3,l0,l1,l2,l3;
        split1hs(v.x,h0,l0); split1hs(v.y,h1,l1);
        split1hs(v.z,h2,l2); split1hs(v.w,h3,l3);
        *(__half2*)(fh + (size_t)j*4)     = __halves2half2(h0,h1);
        *(__half2*)(fh + (size_t)j*4 + 2) = __halves2half2(h2,h3);
        *(__half2*)(fl + (size_t)j*4)     = __halves2half2(l0,l1);
        *(__half2*)(fl + (size_t)j*4 + 2) = __halves2half2(l2,l3);
    }
}

// ============================================================
// Batched NT GEMM, fp16 hi/lo, f16-acc corrections, 3-stage ring.
//   C = alpha * ( Ah*Bh  [f32 acc]
//               + (NTERMS>=2 ? Ah*Bl_scaled : 0)   [f16 acc, /4096 at end]
//               + (NTERMS==3 ? Al_scaled*Bh : 0] ) [f16 acc]
// Block tile 128(M) x 64(N), BK=16, 256 thr, 8 warps as 4x2, warp 32x32.
// MODE 0: fp32 C0.  MODE 1: fp16 hi + scaled-lo Ch/Cl.  MODE 2: fp16 hi only.
// ============================================================
#define PAD 24
#define A_E   (128 * PAD)
#define B_E   (64 * PAD)
#define STG2_E  (2 * A_E + 2 * B_E)
#define GEMM_SMEM (3 * STG2_E * 2)     // 55296 B

template<int MODE, int NTERMS>
__global__ __launch_bounds__(256, 2) void gemm_f16c_nt(
    const __half* __restrict__ Ah, const __half* __restrict__ Al,
    int lda, long sAb, long sAh_,
    const __half* __restrict__ Bh, const __half* __restrict__ Bl,
    int ldb, long sBb, long sBh_,
    float* __restrict__ C0, __half* __restrict__ Ch,
    __half* __restrict__ Cl, int ldc, long sCb, long sCh_,
    int K, float alpha, int HB)
{
    extern __shared__ __half sm[];

    const int z  = blockIdx.z;
    const int zb = z / HB, zh = z % HB;
    Ah += (size_t)zb * sAb + (size_t)zh * sAh_;
    Al += (size_t)zb * sAb + (size_t)zh * sAh_;
    Bh += (size_t)zb * sBb + (size_t)zh * sBh_;
    Bl += (size_t)zb * sBb + (size_t)zh * sBh_;
    const size_t coff = (size_t)zb * sCb + (size_t)zh * sCh_;

    const int tid  = threadIdx.x;
    const int lane = tid & 31;
    const int warp = tid >> 5;
    const int wm   = (warp >> 1) * 32;   // 0,32,64,96
    const int wn   = (warp & 1) * 32;    // 0,32
    const int bm   = blockIdx.y * 128;
    const int bn   = blockIdx.x * 64;

    // loader geometry
    const int arow = tid >> 1;           // 0..127
    const int ach  = (tid & 1) * 8;
    const int brow = (tid & 127) >> 1;   // 0..63 (tid<128 loads B)
    const int bch  = (tid & 1) * 8;

    float acc[2][4][4];
    uint32_t acch[2][4][2];
    #pragma unroll
    for (int i = 0; i < 2; i++)
        #pragma unroll
        for (int j = 0; j < 4; j++) {
            #pragma unroll
            for (int c = 0; c < 4; c++) acc[i][j][c] = 0.f;
            acch[i][j][0] = 0u; acch[i][j][1] = 0u;
        }

    const int lrow16 = lane & 15;
    const int ksub   = (lane >> 4) * 8;
    const int KT = K >> 4;

    const int awo = arow * PAD + ach;
    const int bwo = brow * PAD + bch;

    #pragma unroll
    for (int s = 0; s < 2; s++) {
        if (s < KT) {
            const int k0 = s << 4;
            __half* st = sm + s * STG2_E;
            const size_t ar = (size_t)(bm + arow) * lda + k0 + ach;
            cpasync16(st + awo, Ah + ar);
            if (NTERMS == 3) cpasync16(st + A_E + awo, Al + ar);
            if (tid < 128) {
                const size_t br = (size_t)(bn + brow) * ldb + k0 + bch;
                cpasync16(st + 2*A_E + bwo, Bh + br);
                if (NTERMS >= 2) cpasync16(st + 2*A_E + B_E + bwo, Bl + br);
            }
        }
        CP_COMMIT();
    }

    int st_idx = 0;
    for (int kt = 0; kt < KT; kt++) {
        CP_WAIT1();
        __syncthreads();

        {
            const int kn = kt + 2;
            if (kn < KT) {
                const int k0 = kn << 4;
                int sn = st_idx + 2; if (sn >= 3) sn -= 3;
                __half* st = sm + sn * STG2_E;
                const size_t ar = (size_t)(bm + arow) * lda + k0 + ach;
                cpasync16(st + awo, Ah + ar);
                if (NTERMS == 3) cpasync16(st + A_E + awo, Al + ar);
                if (tid < 128) {
                    const size_t br = (size_t)(bn + brow) * ldb + k0 + bch;
                    cpasync16(st + 2*A_E + bwo, Bh + br);
                    if (NTERMS >= 2) cpasync16(st + 2*A_E + B_E + bwo, Bl + br);
                }
            }
            CP_COMMIT();
        }

        __half* stp = sm + st_idx * STG2_E;
        const int aoff = lrow16 * PAD + ksub;

        uint32_t ah[2][4], bh[4][2];
        #pragma unroll
        for (int np = 0; np < 2; np++) {
            uint32_t r[4];
            ldsm_x4(r, smem_u32(stp + 2*A_E + (wn + np*16)*PAD + aoff));
            bh[2*np][0] = r[0]; bh[2*np+1][0] = r[1];
            bh[2*np][1] = r[2]; bh[2*np+1][1] = r[3];
        }
        #pragma unroll
        for (int mi = 0; mi < 2; mi++)
            ldsm_x4(ah[mi], smem_u32(stp + (wm + mi*16)*PAD + aoff));
        #pragma unroll
        for (int mi = 0; mi < 2; mi++)
            #pragma unroll
            for (int ni = 0; ni < 4; ni++)
                mma_f16_f32(acc[mi][ni], ah[mi], bh[ni][0], bh[ni][1]);

        if (NTERMS >= 2) {
            uint32_t bl[4][2];
            #pragma unroll
            for (int np = 0; np < 2; np++) {
                uint32_t r[4];
                ldsm_x4(r, smem_u32(stp + 2*A_E + B_E + (wn + np*16)*PAD + aoff));
                bl[2*np][0] = r[0]; bl[2*np+1][0] = r[1];
                bl[2*np][1] = r[2]; bl[2*np+1][1] = r[3];
            }
            #pragma unroll
            for (int mi = 0; mi < 2; mi++)
                #pragma unroll
                for (int ni = 0; ni < 4; ni++)
                    mma_f16_f16(acch[mi][ni], ah[mi], bl[ni][0], bl[ni][1]);
        }
        if (NTERMS == 3) {
            #pragma unroll
            for (int mi = 0; mi < 2; mi++)
                ldsm_x4(ah[mi], smem_u32(stp + A_E + (wm + mi*16)*PAD + aoff));
            #pragma unroll
            for (int mi = 0; mi < 2; mi++)
                #pragma unroll
                for (int ni = 0; ni < 4; ni++)
                    mma_f16_f16(acch[mi][ni], ah[mi], bh[ni][0], bh[ni][1]);
        }

        if (++st_idx == 3) st_idx = 0;
    }

    const int g = lane >> 2, tg = lane & 3;
    #pragma unroll
    for (int mi = 0; mi < 2; mi++) {
        const int r0 = bm + wm + mi * 16 + g;
        #pragma unroll
        for (int ni = 0; ni < 4; ni++) {
            const int c0 = bn + wn + ni * 8 + tg * 2;
            float v00 = acc[mi][ni][0], v01 = acc[mi][ni][1];
            float v10 = acc[mi][ni][2], v11 = acc[mi][ni][3];
            if (NTERMS >= 2) {
                __half2 cl0 = *(__half2*)&acch[mi][ni][0];
                __half2 cl1 = *(__half2*)&acch[mi][ni][1];
                v00 += __half2float(__low2half(cl0))  * LO_INV;
                v01 += __half2float(__high2half(cl0)) * LO_INV;
                v10 += __half2float(__low2half(cl1))  * LO_INV;
                v11 += __half2float(__high2half(cl1)) * LO_INV;
            }
            v00 *= alpha; v01 *= alpha; v10 *= alpha; v11 *= alpha;
            if (MODE == 0) {
                *(float2*)&C0[coff + (size_t)r0 * ldc + c0]       = make_float2(v00, v01);
                *(float2*)&C0[coff + (size_t)(r0 + 8) * ldc + c0] = make_float2(v10, v11);
            } else if (MODE == 1) {
                __half h0,h1,l0,l1;
                split1hs(v00,h0,l0); split1hs(v01,h1,l1);
                *(__half2*)(Ch + coff + (size_t)r0 * ldc + c0) = __halves2half2(h0,h1);
                *(__half2*)(Cl + coff + (size_t)r0 * ldc + c0) = __halves2half2(l0,l1);
                split1hs(v10,h0,l0); split1hs(v11,h1,l1);
                *(__half2*)(Ch + coff + (size_t)(r0+8) * ldc + c0) = __halves2half2(h0,h1);
                *(__half2*)(Cl + coff + (size_t)(r0+8) * ldc + c0) = __halves2half2(l0,l1);
            } else {
                *(__half2*)(Ch + coff + (size_t)r0 * ldc + c0) =
                    __halves2half2(__float2half_rn(v00), __float2half_rn(v01));
                *(__half2*)(Ch + coff + (size_t)(r0+8) * ldc + c0) =
                    __halves2half2(__float2half_rn(v10), __float2half_rn(v11));
            }
        }
    }
}

// ============================================================
// Fused softmax + head-mean, online (m,s) reduction: 2 barriers/head.
// fp32 scores -> fp16 probs + fp32 attnw.
// ============================================================
__global__ __launch_bounds__(256) void softmax_mean(
    const float* __restrict__ Sc, __half* __restrict__ Pf,
    float* __restrict__ W)
{
    const int b = blockIdx.x >> 11;
    const int s = blockIdx.x & (S_ - 1);
    const int tid = threadIdx.x;
    const int lane = tid & 31, wid = tid >> 5;

    __shared__ float2 red[8];

    float acc[8];
    #pragma unroll
    for (int i = 0; i < 8; i++) acc[i] = 0.f;

    const int c0 = tid * 4;
    const int c1 = 1024 + tid * 4;

    for (int h = 0; h < H_; h++) {
        const size_t ro = ((size_t)(b * H_ + h) * S_ + s) * S_;
        float v[8];
        float4 f0 = *(const float4*)(Sc + ro + c0);
        float4 f1 = *(const float4*)(Sc + ro + c1);
        v[0]=f0.x; v[1]=f0.y; v[2]=f0.z; v[3]=f0.w;
        v[4]=f1.x; v[5]=f1.y; v[6]=f1.z; v[7]=f1.w;

        // warp-local max
        float mw = v[0];
        #pragma unroll
        for (int i = 1; i < 8; i++) mw = fmaxf(mw, v[i]);
        #pragma unroll
        for (int o = 16; o > 0; o >>= 1) mw = fmaxf(mw, __shfl_xor_sync(0xffffffff, mw, o));

        // warp-local exp + sum
        float e[8], sw = 0.f;
        #pragma unroll
        for (int i = 0; i < 8; i++) { e[i] = __expf(v[i] - mw); sw += e[i]; }
        #pragma unroll
        for (int o = 16; o > 0; o >>= 1) sw += __shfl_xor_sync(0xffffffff, sw, o);

        if (lane == 0) red[wid] = make_float2(mw, sw);
        __syncthreads();

        // combine 8 (m,s) pairs analytically (all threads, no 2nd barrier)
        float M = -1e30f;
        #pragma unroll
        for (int w = 0; w < 8; w++) M = fmaxf(M, red[w].x);
        float S = 0.f;
        #pragma unroll
        for (int w = 0; w < 8; w++) S += red[w].y * __expf(red[w].x - M);
        const float f = __expf(mw - M) / S;   // per-thread: its warp's mw

        __half p16[8];
        #pragma unroll
        for (int i = 0; i < 8; i++) {
            float p = e[i] * f;
            acc[i] += p * (1.0f / H_);
            p16[i] = __float2half_rn(p);
        }
        *(__half2*)(Pf + ro + c0)     = __halves2half2(p16[0], p16[1]);
        *(__half2*)(Pf + ro + c0 + 2) = __halves2half2(p16[2], p16[3]);
        *(__half2*)(Pf + ro + c1)     = __halves2half2(p16[4], p16[5]);
        *(__half2*)(Pf + ro + c1 + 2) = __halves2half2(p16[6], p16[7]);
        __syncthreads();   // protect red[] reuse next head
    }

    float* wrow = W + ((size_t)b * S_ + s) * S_;
    *(float4*)(wrow + c0) = make_float4(acc[0], acc[1], acc[2], acc[3]);
    *(float4*)(wrow + c1) = make_float4(acc[4], acc[5], acc[6], acc[7]);
}

// ============================================================
// attn @ V, fp16 1-term: O = Pf*Vh. 3-stage ring (unchanged from R14).
// ============================================================
#define VPAD 72
#define P_E   (128 * PAD)
#define V_E   (16 * VPAD)
#define AV_STG_E (P_E + V_E)
#define AV_SMEM (3 * AV_STG_E * 2)

__global__ __launch_bounds__(256, 2) void av_hl(
    const __half* __restrict__ Pf,
    const __half* __restrict__ Vh,
    __half* __restrict__ Oh)
{
    extern __shared__ __half smh[];

    const int z = blockIdx.z;
    const int b = z / H_, h = z % H_;
    const size_t po = (size_t)z * S_ * S_;
    const size_t vo = (size_t)b * S_ * D_ + h * DK_;

    const int tid  = threadIdx.x;
    const int lane = tid & 31;
    const int warp = tid >> 5;
    const int wm   = (warp >> 1) * 32;
    const int wn   = (warp & 1) * 32;
    const int bm   = blockIdx.x * 128;

    const int lrow = tid >> 1;
    const int lch  = (tid & 1) * 8;
    const int vrow = tid >> 3;
    const int vch  = (tid & 7) * 8;

    float acc[2][4][4];
    #pragma unroll
    for (int i = 0; i < 2; i++)
        #pragma unroll
        for (int j = 0; j < 4; j++)
            #pragma unroll
            for (int c = 0; c < 4; c++) acc[i][j][c] = 0.f;

    const int lrow16 = lane & 15;
    const int ksub   = (lane >> 4) * 8;
    const int KT = S_ >> 4;

    const int pwo = lrow * PAD + lch;
    const int vwo = vrow * VPAD + vch;

    #pragma unroll
    for (int s = 0; s < 2; s++) {
        const int k0 = s << 4;
        __half* st = smh + s * AV_STG_E;
        cpasync16(st + pwo, Pf + po + (size_t)(bm + lrow) * S_ + k0 + lch);
        if (vrow < 16)
            cpasync16(st + P_E + vwo, Vh + vo + (size_t)(k0 + vrow) * D_ + vch);
        CP_COMMIT();
    }

    int st_idx = 0;
    for (int kt = 0; kt < KT; kt++) {
        CP_WAIT1();
        __syncthreads();

        {
            const int kn = kt + 2;
            if (kn < KT) {
                const int k0 = kn << 4;
                int sn = st_idx + 2; if (sn >= 3) sn -= 3;
                __half* st = smh + sn * AV_STG_E;
                cpasync16(st + pwo, Pf + po + (size_t)(bm + lrow) * S_ + k0 + lch);
                if (vrow < 16)
                    cpasync16(st + P_E + vwo, Vh + vo + (size_t)(k0 + vrow) * D_ + vch);
            }
            CP_COMMIT();
        }

        __half* stp = smh + st_idx * AV_STG_E;

        uint32_t ah[2][4], bh[4][2];
        #pragma unroll
        for (int np = 0; np < 2; np++) {
            uint32_t r[4];
            ldsm_x4_t(r, smem_u32(stp + P_E + lrow16*VPAD + wn + np*16 + ksub));
            bh[2*np][0] = r[0]; bh[2*np][1] = r[1];
            bh[2*np+1][0] = r[2]; bh[2*np+1][1] = r[3];
        }
        #pragma unroll
        for (int mi = 0; mi < 2; mi++)
            ldsm_x4(ah[mi], smem_u32(stp + (wm + mi*16 + lrow16)*PAD + ksub));
        #pragma unroll
        for (int mi = 0; mi < 2; mi++)
            #pragma unroll
            for (int ni = 0; ni < 4; ni++)
                mma_f16_f32(acc[mi][ni], ah[mi], bh[ni][0], bh[ni][1]);

        if (++st_idx == 3) st_idx = 0;
    }

    const int g = lane >> 2, tg = lane & 3;
    #pragma unroll
    for (int mi = 0; mi < 2; mi++) {
        const int r0 = bm + wm + mi * 16 + g;
        #pragma unroll
        for (int ni = 0; ni < 4; ni++) {
            const int c0 = wn + ni * 8 + tg * 2;
            *(__half2*)&Oh[vo + (size_t)r0 * D_ + c0] =
                __halves2half2(__float2half_rn(acc[mi][ni][0]),
                               __float2half_rn(acc[mi][ni][1]));
            *(__half2*)&Oh[vo + (size_t)(r0+8) * D_ + c0] =
                __halves2half2(__float2half_rn(acc[mi][ni][2]),
                               __float2half_rn(acc[mi][ni][3]));
        }
    }
}

// ============================================================
extern "C" void kernel_launch(void* const* d_in, const int* in_sizes, int n_in,
                              void* d_out, int out_size)
{
    const float* query = (const float*)d_in[0];
    const float* key   = (const float*)d_in[1];
    const float* value = (const float*)d_in[2];
    const float* W_q   = (const float*)d_in[3];
    const float* W_k   = (const float*)d_in[4];
    const float* W_v   = (const float*)d_in[5];
    const float* W_o   = (const float*)d_in[6];

    float* out   = (float*)d_out;
    float* attnw = out + (size_t)M_ * D_;

    float *Sc;
    __half *Pf, *Qh, *Ql, *Kh, *Kl, *Vh, *HOh;
    __half *xqh, *xql, *xkh, *xkl, *xvh, *xvl;
    __half *wqh, *wql, *wkh, *wkl, *wvh, *wvl, *woh, *wol;
    cudaGetSymbolAddress((void**)&Sc,  g_S);
    cudaGetSymbolAddress((void**)&Pf,  g_Pf);
    cudaGetSymbolAddress((void**)&Qh,  g_Qh);  cudaGetSymbolAddress((void**)&Ql, g_Ql);
    cudaGetSymbolAddress((void**)&Kh,  g_Kh);  cudaGetSymbolAddress((void**)&Kl, g_Kl);
    cudaGetSymbolAddress((void**)&Vh,  g_Vh);
    cudaGetSymbolAddress((void**)&HOh, g_HOh);
    cudaGetSymbolAddress((void**)&xqh, g_xqh); cudaGetSymbolAddress((void**)&xql, g_xql);
    cudaGetSymbolAddress((void**)&xkh, g_xkh); cudaGetSymbolAddress((void**)&xkl, g_xkl);
    cudaGetSymbolAddress((void**)&xvh, g_xvh); cudaGetSymbolAddress((void**)&xvl, g_xvl);
    cudaGetSymbolAddress((void**)&wqh, g_wqh); cudaGetSymbolAddress((void**)&wql, g_wql);
    cudaGetSymbolAddress((void**)&wkh, g_wkh); cudaGetSymbolAddress((void**)&wkl, g_wkl);
    cudaGetSymbolAddress((void**)&wvh, g_wvh); cudaGetSymbolAddress((void**)&wvl, g_wvl);
    cudaGetSymbolAddress((void**)&woh, g_woh); cudaGetSymbolAddress((void**)&wol, g_wol);

    cudaFuncSetAttribute(gemm_f16c_nt<1,3>, cudaFuncAttributeMaxDynamicSharedMemorySize, GEMM_SMEM);
    cudaFuncSetAttribute(gemm_f16c_nt<2,2>, cudaFuncAttributeMaxDynamicSharedMemorySize, GEMM_SMEM);
    cudaFuncSetAttribute(gemm_f16c_nt<0,3>, cudaFuncAttributeMaxDynamicSharedMemorySize, GEMM_SMEM);
    cudaFuncSetAttribute(gemm_f16c_nt<0,1>, cudaFuncAttributeMaxDynamicSharedMemorySize, GEMM_SMEM);
    cudaFuncSetAttribute(av_hl, cudaFuncAttributeMaxDynamicSharedMemorySize, AV_SMEM);

    dim3 blk(256);

    // 0) split-convert inputs (fp16 hi + scaled lo)
    split_convert_all<<<2048, blk>>>(query, key, value, W_q, W_k, W_v, W_o,
                                     xqh, xql, xkh, xkl, xvh, xvl,
                                     wqh, wql, wkh, wkl, wvh, wvl, woh, wol);

    // 1) Projections: Q,K 3-term -> fp16 split; V 2-term -> fp16 hi only.
    {
        dim3 grid(D_/64, M_/128, 1);
        gemm_f16c_nt<1,3><<<grid, blk, GEMM_SMEM>>>(
            xqh, xql, D_, 0, 0, wqh, wql, D_, 0, 0,
            nullptr, Qh, Ql, D_, 0, 0, D_, 1.0f, 1);
        gemm_f16c_nt<1,3><<<grid, blk, GEMM_SMEM>>>(
            xkh, xkl, D_, 0, 0, wkh, wkl, D_, 0, 0,
            nullptr, Kh, Kl, D_, 0, 0, D_, 1.0f, 1);
        gemm_f16c_nt<2,2><<<grid, blk, GEMM_SMEM>>>(
            xvh, xvh, D_, 0, 0, wvh, wvl, D_, 0, 0,
            nullptr, Vh, nullptr, D_, 0, 0, D_, 1.0f, 1);
    }

    // 2) Scores (fp16 3-term, fp32 out)
    {
        dim3 grid(S_/64, S_/128, B_ * H_);
        gemm_f16c_nt<0,3><<<grid, blk, GEMM_SMEM>>>(
            Qh, Ql, D_, (long)S_ * D_, DK_,
            Kh, Kl, D_, (long)S_ * D_, DK_,
            Sc, nullptr, nullptr, S_, (long)H_ * S_ * S_, (long)S_ * S_,
            DK_, 0.125f, H_);
    }

    // 3) Softmax + head mean (fp16 probs out)
    softmax_mean<<<dim3(B_ * S_), blk>>>(Sc, Pf, attnw);

    // 4) head_out = attn @ V (fp16 1-term)
    av_hl<<<dim3(S_/128, 1, B_ * H_), blk, AV_SMEM>>>(Pf, Vh, HOh);

    // 5) out = head_out @ W_o^T (fp16 1-term, fp32 out)
    {
        dim3 grid(D_/64, M_/128, 1);
        gemm_f16c_nt<0,1><<<grid, blk, GEMM_SMEM>>>(
            HOh, HOh, D_, 0, 0, woh, woh, D_, 0, 0,
            out, nullptr, nullptr, D_, 0, 0, D_, 1.0f, 1);
    }
}

// round 17
// speedup vs baseline: 1.2826x; 1.2826x over previous
#include <cuda_runtime.h>
#include <cuda_bf16.h>
#include <cuda_fp16.h>
#include <math.h>
#include <stdint.h>

#define B_  2
#define S_  2048
#define D_  1024
#define H_  16
#define DK_ 64
#define M_  (B_*S_)   // 4096

// ---- scratch (static device globals; no allocation allowed) ----
__device__ float g_S[(size_t)B_*H_*S_*S_];                 // fp32 scores (512MB)
__device__ __half g_Pf[(size_t)B_*H_*S_*S_];               // probs fp16 (256MB)
__device__ __half g_Qh[(size_t)M_*D_];
__device__ __half g_Kh[(size_t)M_*D_];
__device__ __half g_Vh[(size_t)M_*D_];
__device__ __half g_HOh[(size_t)M_*D_];
__device__ __half g_xqh[(size_t)M_*D_];
__device__ __half g_xkh[(size_t)M_*D_];
__device__ __half g_xvh[(size_t)M_*D_];
__device__ __half g_wqh[(size_t)D_*D_], g_wql[(size_t)D_*D_];
__device__ __half g_wkh[(size_t)D_*D_], g_wkl[(size_t)D_*D_];
__device__ __half g_wvh[(size_t)D_*D_], g_wvl[(size_t)D_*D_];
__device__ __half g_woh[(size_t)D_*D_], g_wol[(size_t)D_*D_];

// ============================================================
// helpers
// ============================================================
__device__ __forceinline__ uint32_t smem_u32(const void* p) {
    return (uint32_t)__cvta_generic_to_shared(p);
}
__device__ __forceinline__ void cpasync16(void* s, const void* g) {
    asm volatile("cp.async.cg.shared.global [%0], [%1], 16;\n"
                 :: "r"(smem_u32(s)), "l"(g));
}
#define CP_COMMIT() asm volatile("cp.async.commit_group;\n" ::)
#define CP_WAIT1()  asm volatile("cp.async.wait_group 1;\n" ::)

__device__ __forceinline__ void ldsm_x4(uint32_t* r, uint32_t a) {
    asm volatile("ldmatrix.sync.aligned.m8n8.x4.shared.b16 {%0,%1,%2,%3}, [%4];"
                 : "=r"(r[0]), "=r"(r[1]), "=r"(r[2]), "=r"(r[3]) : "r"(a));
}
__device__ __forceinline__ void ldsm_x4_t(uint32_t* r, uint32_t a) {
    asm volatile("ldmatrix.sync.aligned.m8n8.x4.trans.shared.b16 {%0,%1,%2,%3}, [%4];"
                 : "=r"(r[0]), "=r"(r[1]), "=r"(r[2]), "=r"(r[3]) : "r"(a));
}
__device__ __forceinline__ void mma_f16_f32(float* c, const uint32_t* a,
                                            uint32_t b0, uint32_t b1) {
    asm volatile(
        "mma.sync.aligned.m16n8k16.row.col.f32.f16.f16.f32 "
        "{%0,%1,%2,%3},{%4,%5,%6,%7},{%8,%9},{%0,%1,%2,%3};"
        : "+f"(c[0]), "+f"(c[1]), "+f"(c[2]), "+f"(c[3])
        : "r"(a[0]), "r"(a[1]), "r"(a[2]), "r"(a[3]), "r"(b0), "r"(b1));
}
__device__ __forceinline__ void split1h(float v, __half& h, __half& l) {
    h = __float2half_rn(v);
    l = __float2half_rn(v - __half2float(h));
}

// ============================================================
// one-shot grid-stride converter:
//   xq,xk,xv -> fp16 hi only ; wq,wk,wv,wo -> fp16 hi/lo
// ============================================================
#define NX4 ((M_*D_)/4)
#define NW4 ((D_*D_)/4)
__global__ __launch_bounds__(256) void split_convert_all(
    const float* __restrict__ xq, const float* __restrict__ xk,
    const float* __restrict__ xv, const float* __restrict__ wq,
    const float* __restrict__ wk, const float* __restrict__ wv,
    const float* __restrict__ wo,
    __half* __restrict__ xqh, __half* __restrict__ xkh, __half* __restrict__ xvh,
    __half* __restrict__ wqh, __half* __restrict__ wql,
    __half* __restrict__ wkh, __half* __restrict__ wkl,
    __half* __restrict__ wvh, __half* __restrict__ wvl,
    __half* __restrict__ woh, __half* __restrict__ wol)
{
    const int total = 3 * NX4 + 4 * NW4;
    for (int i = blockIdx.x * blockDim.x + threadIdx.x; i < total;
         i += gridDim.x * blockDim.x) {
        const float* src; __half *fh = nullptr, *fl = nullptr; int j = i;
        if (j < NX4)               { src = xq; fh = xqh; }
        else if ((j -= NX4) < NX4) { src = xk; fh = xkh; }
        else if ((j -= NX4) < NX4) { src = xv; fh = xvh; }
        else if ((j -= NX4) < NW4) { src = wq; fh = wqh; fl = wql; }
        else if ((j -= NW4) < NW4) { src = wk; fh = wkh; fl = wkl; }
        else if ((j -= NW4) < NW4) { src = wv; fh = wvh; fl = wvl; }
        else      { j -= NW4;        src = wo; fh = woh; fl = wol; }
        float4 v = *(const float4*)(src + (size_t)j * 4);
        __half h0,h1,h2,h3,l0,l1,l2,l3;
        split1h(v.x,h0,l0); split1h(v.y,h1,l1);
        split1h(v.z,h2,l2); split1h(v.w,h3,l3);
        *(__half2*)(fh + (size_t)j*4)     = __halves2half2(h0,h1);
        *(__half2*)(fh + (size_t)j*4 + 2) = __halves2half2(h2,h3);
        if (fl) {
            *(__half2*)(fl + (size_t)j*4)     = __halves2half2(l0,l1);
            *(__half2*)(fl + (size_t)j*4 + 2) = __halves2half2(l2,l3);
        }
    }
}

// ============================================================
// Batched NT GEMM, fp16, f32 acc, 3-stage cp.async ring (R14 geometry).
// NTERMS=2: ah*bh + ah*bl.   NTERMS=1: ah*bh only.
// Block 128x128, BK=16, 256 threads, 8 warps 2x4, warp 64x32.
// MODE 0: fp32 C0.  MODE 2: fp16 hi only Ch.
// ============================================================
#define PAD 24
#define MAT_E   (128 * PAD)
#define STG_E   (4 * MAT_E)
#define GEMM_SMEM (3 * STG_E * 2)

template<int MODE, int NTERMS>
__global__ __launch_bounds__(256, 2) void gemm_hl_nt(
    const __half* __restrict__ Ah,
    int lda, long sAb, long sAh_,
    const __half* __restrict__ Bh, const __half* __restrict__ Bl,
    int ldb, long sBb, long sBh_,
    float* __restrict__ C0, __half* __restrict__ Ch,
    int ldc, long sCb, long sCh_,
    int K, float alpha, int HB)
{
    extern __shared__ __half sm[];

    const int z  = blockIdx.z;
    const int zb = z / HB, zh = z % HB;
    Ah += (size_t)zb * sAb + (size_t)zh * sAh_;
    Bh += (size_t)zb * sBb + (size_t)zh * sBh_;
    Bl += (size_t)zb * sBb + (size_t)zh * sBh_;
    const size_t coff = (size_t)zb * sCb + (size_t)zh * sCh_;

    const int tid  = threadIdx.x;
    const int lane = tid & 31;
    const int warp = tid >> 5;
    const int wm   = (warp >> 2) * 64;
    const int wn   = (warp & 3) * 32;
    const int bm   = blockIdx.y * 128;
    const int bn   = blockIdx.x * 128;

    const int lrow = tid >> 1;
    const int lch  = (tid & 1) * 8;

    float acc[4][4][4];
    #pragma unroll
    for (int i = 0; i < 4; i++)
        #pragma unroll
        for (int j = 0; j < 4; j++)
            #pragma unroll
            for (int c = 0; c < 4; c++) acc[i][j][c] = 0.f;

    const int lrow16 = lane & 15;
    const int ksub   = (lane >> 4) * 8;
    const int KT = K >> 4;
    const int wo_ = lrow * PAD + lch;

    #pragma unroll
    for (int s = 0; s < 2; s++) {
        if (s < KT) {
            const int k0 = s << 4;
            const size_t ar = (size_t)(bm + lrow) * lda + k0 + lch;
            const size_t br = (size_t)(bn + lrow) * ldb + k0 + lch;
            __half* st = sm + s * STG_E;
            cpasync16(st + 0 * MAT_E + wo_, Ah + ar);
            cpasync16(st + 2 * MAT_E + wo_, Bh + br);
            if (NTERMS >= 2) cpasync16(st + 3 * MAT_E + wo_, Bl + br);
        }
        CP_COMMIT();
    }

    int st_idx = 0;
    for (int kt = 0; kt < KT; kt++) {
        CP_WAIT1();
        __syncthreads();

        {
            const int kn = kt + 2;
            if (kn < KT) {
                const int k0 = kn << 4;
                int sn = st_idx + 2; if (sn >= 3) sn -= 3;
                const size_t ar = (size_t)(bm + lrow) * lda + k0 + lch;
                const size_t br = (size_t)(bn + lrow) * ldb + k0 + lch;
                __half* st = sm + sn * STG_E;
                cpasync16(st + 0 * MAT_E + wo_, Ah + ar);
                cpasync16(st + 2 * MAT_E + wo_, Bh + br);
                if (NTERMS >= 2) cpasync16(st + 3 * MAT_E + wo_, Bl + br);
            }
            CP_COMMIT();
        }

        __half* stp = sm + st_idx * STG_E;
        const int aoff = lrow16 * PAD + ksub;

        uint32_t ah[4][4], bh[4][2];
        #pragma unroll
        for (int np = 0; np < 2; np++) {
            uint32_t r[4];
            ldsm_x4(r, smem_u32(stp + 2*MAT_E + (wn + np*16)*PAD + aoff));
            bh[2*np][0] = r[0]; bh[2*np+1][0] = r[1];
            bh[2*np][1] = r[2]; bh[2*np+1][1] = r[3];
        }
        #pragma unroll
        for (int mi = 0; mi < 4; mi++)
            ldsm_x4(ah[mi], smem_u32(stp + 0*MAT_E + (wm + mi*16)*PAD + aoff));
        #pragma unroll
        for (int mi = 0; mi < 4; mi++)
            #pragma unroll
            for (int ni = 0; ni < 4; ni++)
                mma_f16_f32(acc[mi][ni], ah[mi], bh[ni][0], bh[ni][1]);

        if (NTERMS >= 2) {
            uint32_t bl[4][2];
            #pragma unroll
            for (int np = 0; np < 2; np++) {
                uint32_t r[4];
                ldsm_x4(r, smem_u32(stp + 3*MAT_E + (wn + np*16)*PAD + aoff));
                bl[2*np][0] = r[0]; bl[2*np+1][0] = r[1];
                bl[2*np][1] = r[2]; bl[2*np+1][1] = r[3];
            }
            #pragma unroll
            for (int mi = 0; mi < 4; mi++)
                #pragma unroll
                for (int ni = 0; ni < 4; ni++)
                    mma_f16_f32(acc[mi][ni], ah[mi], bl[ni][0], bl[ni][1]);
        }

        if (++st_idx == 3) st_idx = 0;
    }

    const int g = lane >> 2, tg = lane & 3;
    #pragma unroll
    for (int mi = 0; mi < 4; mi++) {
        const int r0 = bm + wm + mi * 16 + g;
        #pragma unroll
        for (int ni = 0; ni < 4; ni++) {
            const int c0 = bn + wn + ni * 8 + tg * 2;
            float v00 = alpha * acc[mi][ni][0], v01 = alpha * acc[mi][ni][1];
            float v10 = alpha * acc[mi][ni][2], v11 = alpha * acc[mi][ni][3];
            if (MODE == 0) {
                *(float2*)&C0[coff + (size_t)r0 * ldc + c0]       = make_float2(v00, v01);
                *(float2*)&C0[coff + (size_t)(r0 + 8) * ldc + c0] = make_float2(v10, v11);
            } else {
                *(__half2*)(Ch + coff + (size_t)r0 * ldc + c0) =
                    __halves2half2(__float2half_rn(v00), __float2half_rn(v01));
                *(__half2*)(Ch + coff + (size_t)(r0+8) * ldc + c0) =
                    __halves2half2(__float2half_rn(v10), __float2half_rn(v11));
            }
        }
    }
}

// ============================================================
// Fused softmax + head-mean, online (m,s) reduction (exact).
// fp32 scores -> fp16 probs + fp32 attnw.
// ============================================================
__global__ __launch_bounds__(256) void softmax_mean(
    const float* __restrict__ Sc, __half* __restrict__ Pf,
    float* __restrict__ W)
{
    const int b = blockIdx.x >> 11;
    const int s = blockIdx.x & (S_ - 1);
    const int tid = threadIdx.x;
    const int lane = tid & 31, wid = tid >> 5;

    __shared__ float2 red[8];

    float acc[8];
    #pragma unroll
    for (int i = 0; i < 8; i++) acc[i] = 0.f;

    const int c0 = tid * 4;
    const int c1 = 1024 + tid * 4;

    for (int h = 0; h < H_; h++) {
        const size_t ro = ((size_t)(b * H_ + h) * S_ + s) * S_;
        float v[8];
        float4 f0 = *(const float4*)(Sc + ro + c0);
        float4 f1 = *(const float4*)(Sc + ro + c1);
        v[0]=f0.x; v[1]=f0.y; v[2]=f0.z; v[3]=f0.w;
        v[4]=f1.x; v[5]=f1.y; v[6]=f1.z; v[7]=f1.w;

        float mw = v[0];
        #pragma unroll
        for (int i = 1; i < 8; i++) mw = fmaxf(mw, v[i]);
        #pragma unroll
        for (int o = 16; o > 0; o >>= 1) mw = fmaxf(mw, __shfl_xor_sync(0xffffffff, mw, o));

        float e[8], sw = 0.f;
        #pragma unroll
        for (int i = 0; i < 8; i++) { e[i] = __expf(v[i] - mw); sw += e[i]; }
        #pragma unroll
        for (int o = 16; o > 0; o >>= 1) sw += __shfl_xor_sync(0xffffffff, sw, o);

        if (lane == 0) red[wid] = make_float2(mw, sw);
        __syncthreads();

        float M = -1e30f;
        #pragma unroll
        for (int w = 0; w < 8; w++) M = fmaxf(M, red[w].x);
        float S = 0.f;
        #pragma unroll
        for (int w = 0; w < 8; w++) S += red[w].y * __expf(red[w].x - M);
        const float f = __expf(mw - M) / S;

        __half p16[8];
        #pragma unroll
        for (int i = 0; i < 8; i++) {
            float p = e[i] * f;
            acc[i] += p * (1.0f / H_);
            p16[i] = __float2half_rn(p);
        }
        *(__half2*)(Pf + ro + c0)     = __halves2half2(p16[0], p16[1]);
        *(__half2*)(Pf + ro + c0 + 2) = __halves2half2(p16[2], p16[3]);
        *(__half2*)(Pf + ro + c1)     = __halves2half2(p16[4], p16[5]);
        *(__half2*)(Pf + ro + c1 + 2) = __halves2half2(p16[6], p16[7]);
        __syncthreads();
    }

    float* wrow = W + ((size_t)b * S_ + s) * S_;
    *(float4*)(wrow + c0) = make_float4(acc[0], acc[1], acc[2], acc[3]);
    *(float4*)(wrow + c1) = make_float4(acc[4], acc[5], acc[6], acc[7]);
}

// ============================================================
// attn @ V, fp16 1-term: O = Pf*Vh. 3-stage ring (R14 version).
// ============================================================
#define VPAD 72
#define P_E   (128 * PAD)
#define V_E   (16 * VPAD)
#define AV_STG_E (P_E + V_E)
#define AV_SMEM (3 * AV_STG_E * 2)

__global__ __launch_bounds__(256, 2) void av_hl(
    const __half* __restrict__ Pf,
    const __half* __restrict__ Vh,
    __half* __restrict__ Oh)
{
    extern __shared__ __half smh[];

    const int z = blockIdx.z;
    const int b = z / H_, h = z % H_;
    const size_t po = (size_t)z * S_ * S_;
    const size_t vo = (size_t)b * S_ * D_ + h * DK_;

    const int tid  = threadIdx.x;
    const int lane = tid & 31;
    const int warp = tid >> 5;
    const int wm   = (warp >> 1) * 32;
    const int wn   = (warp & 1) * 32;
    const int bm   = blockIdx.x * 128;

    const int lrow = tid >> 1;
    const int lch  = (tid & 1) * 8;
    const int vrow = tid >> 3;
    const int vch  = (tid & 7) * 8;

    float acc[2][4][4];
    #pragma unroll
    for (int i = 0; i < 2; i++)
        #pragma unroll
        for (int j = 0; j < 4; j++)
            #pragma unroll
            for (int c = 0; c < 4; c++) acc[i][j][c] = 0.f;

    const int lrow16 = lane & 15;
    const int ksub   = (lane >> 4) * 8;
    const int KT = S_ >> 4;

    const int pwo = lrow * PAD + lch;
    const int vwo = vrow * VPAD + vch;

    #pragma unroll
    for (int s = 0; s < 2; s++) {
        const int k0 = s << 4;
        __half* st = smh + s * AV_STG_E;
        cpasync16(st + pwo, Pf + po + (size_t)(bm + lrow) * S_ + k0 + lch);
        if (vrow < 16)
            cpasync16(st + P_E + vwo, Vh + vo + (size_t)(k0 + vrow) * D_ + vch);
        CP_COMMIT();
    }

    int st_idx = 0;
    for (int kt = 0; kt < KT; kt++) {
        CP_WAIT1();
        __syncthreads();

        {
            const int kn = kt + 2;
            if (kn < KT) {
                const int k0 = kn << 4;
                int sn = st_idx + 2; if (sn >= 3) sn -= 3;
                __half* st = smh + sn * AV_STG_E;
                cpasync16(st + pwo, Pf + po + (size_t)(bm + lrow) * S_ + k0 + lch);
                if (vrow < 16)
                    cpasync16(st + P_E + vwo, Vh + vo + (size_t)(k0 + vrow) * D_ + vch);
            }
            CP_COMMIT();
        }

        __half* stp = smh + st_idx * AV_STG_E;

        uint32_t ah[2][4], bh[4][2];
        #pragma unroll
        for (int np = 0; np < 2; np++) {
            uint32_t r[4];
            ldsm_x4_t(r, smem_u32(stp + P_E + lrow16*VPAD + wn + np*16 + ksub));
            bh[2*np][0] = r[0]; bh[2*np][1] = r[1];
            bh[2*np+1][0] = r[2]; bh[2*np+1][1] = r[3];
        }
        #pragma unroll
        for (int mi = 0; mi < 2; mi++)
            ldsm_x4(ah[mi], smem_u32(stp + (wm + mi*16 + lrow16)*PAD + ksub));
        #pragma unroll
        for (int mi = 0; mi < 2; mi++)
            #pragma unroll
            for (int ni = 0; ni < 4; ni++)
                mma_f16_f32(acc[mi][ni], ah[mi], bh[ni][0], bh[ni][1]);

        if (++st_idx == 3) st_idx = 0;
    }

    const int g = lane >> 2, tg = lane & 3;
    #pragma unroll
    for (int mi = 0; mi < 2; mi++) {
        const int r0 = bm + wm + mi * 16 + g;
        #pragma unroll
        for (int ni = 0; ni < 4; ni++) {
            const int c0 = wn + ni * 8 + tg * 2;
            *(__half2*)&Oh[vo + (size_t)r0 * D_ + c0] =
                __halves2half2(__float2half_rn(acc[mi][ni][0]),
                               __float2half_rn(acc[mi][ni][1]));
            *(__half2*)&Oh[vo + (size_t)(r0+8) * D_ + c0] =
                __halves2half2(__float2half_rn(acc[mi][ni][2]),
                               __float2half_rn(acc[mi][ni][3]));
        }
    }
}

// ============================================================
extern "C" void kernel_launch(void* const* d_in, const int* in_sizes, int n_in,
                              void* d_out, int out_size)
{
    const float* query = (const float*)d_in[0];
    const float* key   = (const float*)d_in[1];
    const float* value = (const float*)d_in[2];
    const float* W_q   = (const float*)d_in[3];
    const float* W_k   = (const float*)d_in[4];
    const float* W_v   = (const float*)d_in[5];
    const float* W_o   = (const float*)d_in[6];

    float* out   = (float*)d_out;
    float* attnw = out + (size_t)M_ * D_;

    float *Sc;
    __half *Pf, *Qh, *Kh, *Vh, *HOh;
    __half *xqh, *xkh, *xvh;
    __half *wqh, *wql, *wkh, *wkl, *wvh, *wvl, *woh, *wol;
    cudaGetSymbolAddress((void**)&Sc,  g_S);
    cudaGetSymbolAddress((void**)&Pf,  g_Pf);
    cudaGetSymbolAddress((void**)&Qh,  g_Qh);
    cudaGetSymbolAddress((void**)&Kh,  g_Kh);
    cudaGetSymbolAddress((void**)&Vh,  g_Vh);
    cudaGetSymbolAddress((void**)&HOh, g_HOh);
    cudaGetSymbolAddress((void**)&xqh, g_xqh);
    cudaGetSymbolAddress((void**)&xkh, g_xkh);
    cudaGetSymbolAddress((void**)&xvh, g_xvh);
    cudaGetSymbolAddress((void**)&wqh, g_wqh); cudaGetSymbolAddress((void**)&wql, g_wql);
    cudaGetSymbolAddress((void**)&wkh, g_wkh); cudaGetSymbolAddress((void**)&wkl, g_wkl);
    cudaGetSymbolAddress((void**)&wvh, g_wvh); cudaGetSymbolAddress((void**)&wvl, g_wvl);
    cudaGetSymbolAddress((void**)&woh, g_woh); cudaGetSymbolAddress((void**)&wol, g_wol);

    cudaFuncSetAttribute(gemm_hl_nt<2,2>, cudaFuncAttributeMaxDynamicSharedMemorySize, GEMM_SMEM);
    cudaFuncSetAttribute(gemm_hl_nt<0,2>, cudaFuncAttributeMaxDynamicSharedMemorySize, GEMM_SMEM);
    cudaFuncSetAttribute(gemm_hl_nt<0,1>, cudaFuncAttributeMaxDynamicSharedMemorySize, GEMM_SMEM);
    cudaFuncSetAttribute(av_hl, cudaFuncAttributeMaxDynamicSharedMemorySize, AV_SMEM);

    dim3 blk(256);

    // 0) split-convert inputs
    split_convert_all<<<2048, blk>>>(query, key, value, W_q, W_k, W_v, W_o,
                                     xqh, xkh, xvh,
                                     wqh, wql, wkh, wkl, wvh, wvl, woh, wol);

    // 1) Projections: fp16 2-term (xh*(wh+wl)), hi-only out.
    {
        dim3 grid(D_/128, M_/128, 1);
        gemm_hl_nt<2,2><<<grid, blk, GEMM_SMEM>>>(
            xqh, D_, 0, 0, wqh, wql, D_, 0, 0,
            nullptr, Qh, D_, 0, 0, D_, 1.0f, 1);
        gemm_hl_nt<2,2><<<grid, blk, GEMM_SMEM>>>(
            xkh, D_, 0, 0, wkh, wkl, D_, 0, 0,
            nullptr, Kh, D_, 0, 0, D_, 1.0f, 1);
        gemm_hl_nt<2,2><<<grid, blk, GEMM_SMEM>>>(
            xvh, D_, 0, 0, wvh, wvl, D_, 0, 0,
            nullptr, Vh, D_, 0, 0, D_, 1.0f, 1);
    }

    // 2) Scores: fp16 1-term (Qh*Kh), fp32 out.
    {
        dim3 grid(S_/128, S_/128, B_ * H_);
        gemm_hl_nt<0,1><<<grid, blk, GEMM_SMEM>>>(
            Qh, D_, (long)S_ * D_, DK_,
            Kh, Kh, D_, (long)S_ * D_, DK_,
            Sc, nullptr, S_, (long)H_ * S_ * S_, (long)S_ * S_,
            DK_, 0.125f, H_);
    }

    // 3) Softmax + head mean (fp16 probs out)
    softmax_mean<<<dim3(B_ * S_), blk>>>(Sc, Pf, attnw);

    // 4) head_out = attn @ V (fp16 1-term)
    av_hl<<<dim3(S_/128, 1, B_ * H_), blk, AV_SMEM>>>(Pf, Vh, HOh);

    // 5) out = head_out @ W_o^T (fp16 2-term, fp32 out)
    {
        dim3 grid(D_/128, M_/128, 1);
        gemm_hl_nt<0,2><<<grid, blk, GEMM_SMEM>>>(
            HOh, D_, 0, 0, woh, wol, D_, 0, 0,
            out, nullptr, D_, 0, 0, D_, 1.0f, 1);
    }
}